// round 1
// baseline (speedup 1.0000x reference)
#include <cuda_runtime.h>
#include <stdint.h>

#define N_HITS  8192
#define E_MAXSZ 8192
#define ROW_CAP 64
#define TRK_CAP 128

// Output layout (float32 elements), tuple flattened in order:
// X (8192x3), Ri (8192x8192), Ro (8192x8192), y (8192), edges (8192x2), edge_mask (8192)
#define OFF_X     ((size_t)0)
#define OFF_RI    ((size_t)24576)
#define OFF_RO    (OFF_RI + (size_t)N_HITS * (size_t)E_MAXSZ)
#define OFF_Y     (OFF_RO + (size_t)N_HITS * (size_t)E_MAXSZ)
#define OFF_EDGES (OFF_Y + (size_t)E_MAXSZ)
#define OFF_MASK  (OFF_EDGES + (size_t)2 * E_MAXSZ)

// ---- scratch (device globals; no allocations allowed) ----
__device__ float  g_phin[N_HITS];
__device__ float  g_zn[N_HITS];
__device__ float  g_track[N_HITS];
__device__ float  g_ev[N_HITS];
__device__ int    g_st[N_HITS];

__device__ int    g_stcnt[32];
__device__ float4 g_stdata[32][N_HITS];     // {phin, zn, idx_as_float_bits, ev}

__device__ int    g_trkcnt[1024];
__device__ int    g_trkbucket[1024][TRK_CAP];

__device__ int    g_rowcnt[N_HITS];
__device__ int    g_rowoff[N_HITS];
__device__ int    g_rowj[N_HITS][ROW_CAP];
__device__ int    g_count;
__device__ int    g_src[E_MAXSZ];
__device__ int    g_dst[E_MAXSZ];

// ---------------------------------------------------------------------------
// Kernel 1: per-hit normalize, write X, stash scratch, zero counters
// ---------------------------------------------------------------------------
__global__ void k_prep(const float* __restrict__ ed, float* __restrict__ out) {
    int i = blockIdx.x * blockDim.x + threadIdx.x;
    if (i < 32)   g_stcnt[i]  = 0;
    if (i < 1024) g_trkcnt[i] = 0;
    if (i >= N_HITS) return;

    float ev  = ed[6 * i + 0];
    float x   = ed[6 * i + 1];
    float y   = ed[6 * i + 2];
    float z   = ed[6 * i + 3];
    float stf = ed[6 * i + 4];
    float trk = ed[6 * i + 5];

    // IEEE-exact f32 path (no fma contraction, rn division/sqrt)
    float xx = __fmul_rn(x, x);
    float yy = __fmul_rn(y, y);
    float r  = __fsqrt_rn(__fadd_rn(xx, yy));
    float phi = atan2f(x, y);                   // matches XLA libdevice atan2

    float rn   = __fadd_rn(__fdiv_rn(__fmul_rn(2.0f, __fadd_rn(r,  -269.0f)),  312.0f), -1.0f);
    float phin = __fadd_rn(__fdiv_rn(__fmul_rn(2.0f, __fadd_rn(phi,  3.15f)),    6.3f), -1.0f);
    float zn   = __fadd_rn(__fdiv_rn(__fmul_rn(2.0f, __fadd_rn(z,  2386.0f)),  4772.0f), -1.0f);

    out[OFF_X + 3 * (size_t)i + 0] = rn;
    out[OFF_X + 3 * (size_t)i + 1] = phin;
    out[OFF_X + 3 * (size_t)i + 2] = zn;

    g_phin[i]  = phin;
    g_zn[i]    = zn;
    g_track[i] = trk;
    g_ev[i]    = ev;
    g_st[i]    = (int)stf;
}

// ---------------------------------------------------------------------------
// Kernel 2: bucket hits by station (packed candidate data) and by track id
// ---------------------------------------------------------------------------
__global__ void k_bucket(void) {
    int i = blockIdx.x * blockDim.x + threadIdx.x;
    if (i >= N_HITS) return;

    int st = g_st[i];
    if (st >= 0 && st < 32) {
        int slot = atomicAdd(&g_stcnt[st], 1);
        float4 d;
        d.x = g_phin[i];
        d.y = g_zn[i];
        d.z = __int_as_float(i);
        d.w = g_ev[i];
        g_stdata[st][slot] = d;
    }
    int t = (int)g_track[i];
    if (t >= 0 && t < 1024) {
        int s2 = atomicAdd(&g_trkcnt[t], 1);
        if (s2 < TRK_CAP) g_trkbucket[t][s2] = i;
    }
}

// ---------------------------------------------------------------------------
// Kernel 3: per-row candidate scan (station s+1), collect + sort matches
// ---------------------------------------------------------------------------
__global__ void k_pairs(void) {
    int i = blockIdx.x * blockDim.x + threadIdx.x;
    if (i >= N_HITS) return;

    int mj[ROW_CAP];
    int cnt = 0;

    int s2 = g_st[i] + 1;
    if (s2 >= 0 && s2 < 32) {
        int n2 = g_stcnt[s2];
        float pi  = g_phin[i];
        float zi  = g_zn[i];
        float evi = g_ev[i];
        for (int k = 0; k < n2; k++) {
            float4 c = g_stdata[s2][k];
            float dphi = c.x - pi;
            float dz   = c.y - zi;
            bool ok = (c.w == evi) &
                      (dphi > -0.04f) & (dphi < 0.04f) &
                      (dz   > -0.03f) & (dz   < 0.03f);
            if (ok) {
                if (cnt < ROW_CAP) mj[cnt] = __float_as_int(c.z);
                cnt++;
            }
        }
    }
    if (cnt > ROW_CAP) cnt = ROW_CAP;

    // insertion sort ascending (bucket order is nondeterministic; this
    // restores exact row-major nonzero order and makes output deterministic)
    for (int a = 1; a < cnt; a++) {
        int v = mj[a];
        int b = a - 1;
        while (b >= 0 && mj[b] > v) { mj[b + 1] = mj[b]; b--; }
        mj[b + 1] = v;
    }
    for (int m = 0; m < cnt; m++) g_rowj[i][m] = mj[m];
    g_rowcnt[i] = cnt;
}

// ---------------------------------------------------------------------------
// Kernel 4: exclusive prefix sum of row counts (single block, 1024 thr x 8)
// ---------------------------------------------------------------------------
__global__ void k_scan(void) {
    __shared__ int s[1024];
    int t = threadIdx.x;
    int base = t * 8;
    int loc[8];
    int acc = 0;
    #pragma unroll
    for (int m = 0; m < 8; m++) { loc[m] = g_rowcnt[base + m]; acc += loc[m]; }
    s[t] = acc;
    __syncthreads();
    // Hillis-Steele inclusive scan
    for (int off = 1; off < 1024; off <<= 1) {
        int v = (t >= off) ? s[t - off] : 0;
        __syncthreads();
        s[t] += v;
        __syncthreads();
    }
    int excl = s[t] - acc;   // exclusive prefix for this thread's chunk
    int run = excl;
    #pragma unroll
    for (int m = 0; m < 8; m++) { g_rowoff[base + m] = run; run += loc[m]; }
    if (t == 1023) g_count = s[1023];
}

// ---------------------------------------------------------------------------
// Kernel 5: emit edges (track values), mask, and src/dst hit indices
// ---------------------------------------------------------------------------
__global__ void k_emit(float* __restrict__ out) {
    int i = blockIdx.x * blockDim.x + threadIdx.x;
    if (i >= N_HITS) return;
    int cnt = g_rowcnt[i];
    int off = g_rowoff[i];
    float ti = g_track[i];
    for (int m = 0; m < cnt; m++) {
        int e = off + m;
        if (e < E_MAXSZ) {
            int j = g_rowj[i][m];
            out[OFF_EDGES + 2 * (size_t)e + 0] = ti;
            out[OFF_EDGES + 2 * (size_t)e + 1] = g_track[j];
            out[OFF_MASK + (size_t)e] = 1.0f;
            g_src[e] = i;
            g_dst[e] = j;
        }
    }
}

// ---------------------------------------------------------------------------
// Kernel 6: fill unused edge slots with track[src=0]=track[0] (nonzero fill_value=0)
// ---------------------------------------------------------------------------
__global__ void k_fill(float* __restrict__ out) {
    int e = blockIdx.x * blockDim.x + threadIdx.x;
    if (e >= E_MAXSZ) return;
    if (e >= g_count) {
        float t0 = g_track[0];
        out[OFF_EDGES + 2 * (size_t)e + 0] = t0;
        out[OFF_EDGES + 2 * (size_t)e + 1] = t0;
        // mask stays 0 from the memset
    }
}

// ---------------------------------------------------------------------------
// Kernel 7: sparse scatter of Ri/Ro ones. One warp per edge slot.
// Ri[i][e] = 1 where track[i] == track[dst[e]];  Ro via src[e].
// ---------------------------------------------------------------------------
__global__ void k_riro(float* __restrict__ out) {
    int gtid = blockIdx.x * blockDim.x + threadIdx.x;
    int e = gtid >> 5;
    int lane = gtid & 31;
    if (e >= E_MAXSZ) return;
    if (e >= g_count) return;

    int ts = (int)g_track[g_src[e]];
    int n = g_trkcnt[ts]; if (n > TRK_CAP) n = TRK_CAP;
    for (int k = lane; k < n; k += 32) {
        int i = g_trkbucket[ts][k];
        out[OFF_RO + (size_t)i * E_MAXSZ + (size_t)e] = 1.0f;
    }

    int td = (int)g_track[g_dst[e]];
    n = g_trkcnt[td]; if (n > TRK_CAP) n = TRK_CAP;
    for (int k = lane; k < n; k += 32) {
        int i = g_trkbucket[td][k];
        out[OFF_RI + (size_t)i * E_MAXSZ + (size_t)e] = 1.0f;
    }
}

// ---------------------------------------------------------------------------
extern "C" void kernel_launch(void* const* d_in, const int* in_sizes, int n_in,
                              void* d_out, int out_size) {
    const float* ed = (const float*)d_in[0];
    float* out = (float*)d_out;

    // Zero the entire output (Ri/Ro are ~all zeros; y_lbl is zeros; edge_mask
    // default false). This is the dominant cost: ~537 MB of stores.
    cudaMemsetAsync(d_out, 0, (size_t)out_size * sizeof(float), 0);

    k_prep  <<<32, 256>>>(ed, out);
    k_bucket<<<32, 256>>>();
    k_pairs <<<32, 256>>>();
    k_scan  <<<1, 1024>>>();
    k_emit  <<<32, 256>>>(out);
    k_fill  <<<32, 256>>>(out);
    k_riro  <<<(E_MAXSZ * 32 + 255) / 256, 256>>>(out);
}

// round 2
// speedup vs baseline: 1.1494x; 1.1494x over previous
#include <cuda_runtime.h>
#include <stdint.h>

#define N_HITS  8192
#define E_MAXSZ 8192
#define ROW_CAP 64
#define LIST_CAP 64

// Output layout (float32 elements), tuple flattened in order:
// X (8192x3), Ri (8192x8192), Ro (8192x8192), y (8192), edges (8192x2), edge_mask (8192)
#define OFF_X     ((size_t)0)
#define OFF_RI    ((size_t)24576)
#define OFF_RO    (OFF_RI + (size_t)N_HITS * (size_t)E_MAXSZ)
#define OFF_Y     (OFF_RO + (size_t)N_HITS * (size_t)E_MAXSZ)
#define OFF_EDGES (OFF_Y + (size_t)E_MAXSZ)
#define OFF_MASK  (OFF_EDGES + (size_t)2 * E_MAXSZ)

// ---- scratch (device globals; no allocations allowed) ----
__device__ float  g_phin[N_HITS];
__device__ float  g_zn[N_HITS];
__device__ float  g_track[N_HITS];
__device__ int    g_trkInt[N_HITS];
__device__ float  g_ev[N_HITS];
__device__ int    g_st[N_HITS];

__device__ int    g_stcnt[32];
__device__ float4 g_stdata[32][N_HITS];     // {phin, zn, idx_bits, ev}

__device__ int    g_rowcnt[N_HITS];
__device__ int    g_rowj[N_HITS][ROW_CAP];

// per-track edge lists for the fused zero+scatter pass
__device__ int    g_inCnt[1024];            // edges e with track[dst[e]] == t  -> Ri rows
__device__ int    g_outCnt[1024];           // edges e with track[src[e]] == t  -> Ro rows
__device__ int    g_inList[1024][LIST_CAP];
__device__ int    g_outList[1024][LIST_CAP];

// ---------------------------------------------------------------------------
// K0: reset counters (must run every call: graph replays reuse globals)
// ---------------------------------------------------------------------------
__global__ void k_reset(void) {
    int t = threadIdx.x;
    if (t < 32) g_stcnt[t] = 0;
    g_inCnt[t]  = 0;
    g_outCnt[t] = 0;
}

// ---------------------------------------------------------------------------
// K1: per-hit normalize (write X), bucket by station
// ---------------------------------------------------------------------------
__global__ void k_prep(const float* __restrict__ ed, float* __restrict__ out) {
    int i = blockIdx.x * blockDim.x + threadIdx.x;
    if (i >= N_HITS) return;

    float ev  = ed[6 * i + 0];
    float x   = ed[6 * i + 1];
    float y   = ed[6 * i + 2];
    float z   = ed[6 * i + 3];
    float stf = ed[6 * i + 4];
    float trk = ed[6 * i + 5];

    // IEEE-exact f32 path (no fma contraction, rn division/sqrt)
    float xx = __fmul_rn(x, x);
    float yy = __fmul_rn(y, y);
    float r  = __fsqrt_rn(__fadd_rn(xx, yy));
    float phi = atan2f(x, y);

    float rn   = __fadd_rn(__fdiv_rn(__fmul_rn(2.0f, __fadd_rn(r,  -269.0f)),  312.0f), -1.0f);
    float phin = __fadd_rn(__fdiv_rn(__fmul_rn(2.0f, __fadd_rn(phi,  3.15f)),    6.3f), -1.0f);
    float zn   = __fadd_rn(__fdiv_rn(__fmul_rn(2.0f, __fadd_rn(z,  2386.0f)),  4772.0f), -1.0f);

    out[OFF_X + 3 * (size_t)i + 0] = rn;
    out[OFF_X + 3 * (size_t)i + 1] = phin;
    out[OFF_X + 3 * (size_t)i + 2] = zn;

    g_phin[i]   = phin;
    g_zn[i]     = zn;
    g_track[i]  = trk;
    g_trkInt[i] = (int)trk;
    g_ev[i]     = ev;
    int st      = (int)stf;
    g_st[i]     = st;

    if (st >= 0 && st < 32) {
        int slot = atomicAdd(&g_stcnt[st], 1);
        float4 d;
        d.x = phin; d.y = zn; d.z = __int_as_float(i); d.w = ev;
        g_stdata[st][slot] = d;
    }
}

// ---------------------------------------------------------------------------
// K2: warp-per-row candidate scan against station st+1; sort matches by j
// ---------------------------------------------------------------------------
__global__ void k_pairs(void) {
    int gtid = blockIdx.x * blockDim.x + threadIdx.x;
    int row  = gtid >> 5;
    int lane = gtid & 31;
    if (row >= N_HITS) return;

    int myMatch[16];
    int mycnt = 0;

    int s2 = g_st[row] + 1;
    if (s2 >= 0 && s2 < 32) {
        int n2 = g_stcnt[s2];
        float pi  = g_phin[row];
        float zi  = g_zn[row];
        float evi = g_ev[row];
        for (int k = lane; k < n2; k += 32) {
            float4 c = g_stdata[s2][k];
            float dphi = c.x - pi;
            float dz   = c.y - zi;
            bool ok = (c.w == evi) &
                      (dphi > -0.04f) & (dphi < 0.04f) &
                      (dz   > -0.03f) & (dz   < 0.03f);
            if (ok && mycnt < 16) myMatch[mycnt++] = __float_as_int(c.z);
        }
    }

    // warp exclusive scan of per-lane counts
    int off = mycnt;
    #pragma unroll
    for (int d = 1; d < 32; d <<= 1) {
        int v = __shfl_up_sync(0xFFFFFFFFu, off, d);
        if (lane >= d) off += v;
    }
    int total = __shfl_sync(0xFFFFFFFFu, off, 31);
    int excl  = off - mycnt;
    for (int m = 0; m < mycnt; m++) {
        int e = excl + m;
        if (e < ROW_CAP) g_rowj[row][e] = myMatch[m];
    }
    __syncwarp();

    if (lane == 0) {
        int cnt = total < ROW_CAP ? total : ROW_CAP;
        // insertion sort ascending by j (bucket order is nondeterministic;
        // this restores exact row-major nonzero order)
        for (int a = 1; a < cnt; a++) {
            int v = g_rowj[row][a];
            int b = a - 1;
            while (b >= 0 && g_rowj[row][b] > v) { g_rowj[row][b + 1] = g_rowj[row][b]; b--; }
            g_rowj[row][b + 1] = v;
        }
        g_rowcnt[row] = cnt;
    }
}

// ---------------------------------------------------------------------------
// K3: fused scan + emit + fill + mask + y  (single block, 1024 threads)
// ---------------------------------------------------------------------------
__global__ void k_scan_emit(float* __restrict__ out) {
    __shared__ int warpTot[32];
    __shared__ int s_count;
    int tid  = threadIdx.x;
    int lane = tid & 31;
    int wid  = tid >> 5;

    // each thread owns 8 rows
    int base = tid * 8;
    int loc[8];
    int acc = 0;
    #pragma unroll
    for (int m = 0; m < 8; m++) { loc[m] = g_rowcnt[base + m]; acc += loc[m]; }

    // warp inclusive scan of per-thread sums
    int inc = acc;
    #pragma unroll
    for (int d = 1; d < 32; d <<= 1) {
        int v = __shfl_up_sync(0xFFFFFFFFu, inc, d);
        if (lane >= d) inc += v;
    }
    if (lane == 31) warpTot[wid] = inc;
    __syncthreads();
    if (wid == 0) {
        int w = (lane < 32) ? warpTot[lane] : 0;
        int wi = w;
        #pragma unroll
        for (int d = 1; d < 32; d <<= 1) {
            int v = __shfl_up_sync(0xFFFFFFFFu, wi, d);
            if (lane >= d) wi += v;
        }
        warpTot[lane] = wi - w;   // exclusive warp offsets
        if (lane == 31) s_count = wi;
    }
    __syncthreads();
    int excl = inc - acc + warpTot[wid];   // exclusive prefix for this thread
    int count = s_count;

    // emit this thread's rows
    int run = excl;
    #pragma unroll
    for (int m = 0; m < 8; m++) {
        int i = base + m;
        int cnt = loc[m];
        float ti = g_track[i];
        int tsI = g_trkInt[i];
        for (int q = 0; q < cnt; q++) {
            int e = run + q;
            if (e < E_MAXSZ) {
                int j = g_rowj[i][q];
                out[OFF_EDGES + 2 * (size_t)e + 0] = ti;
                out[OFF_EDGES + 2 * (size_t)e + 1] = g_track[j];
                out[OFF_MASK + (size_t)e] = 1.0f;
                // per-track edge lists for the Ri/Ro scatter
                int tdI = g_trkInt[j];
                int so = atomicAdd(&g_outCnt[tsI], 1);
                if (so < LIST_CAP) g_outList[tsI][so] = e;
                int si = atomicAdd(&g_inCnt[tdI], 1);
                if (si < LIST_CAP) g_inList[tdI][si] = e;
            }
        }
        run += cnt;
    }

    // fill unused edge slots (nonzero fill_value=0 -> track[0]) + mask zeros + y zeros
    float t0 = g_track[0];
    #pragma unroll
    for (int m = 0; m < 8; m++) {
        int e = base + m;
        out[OFF_Y + (size_t)e] = 0.0f;
        if (e >= count) {
            out[OFF_EDGES + 2 * (size_t)e + 0] = t0;
            out[OFF_EDGES + 2 * (size_t)e + 1] = t0;
            out[OFF_MASK + (size_t)e] = 0.0f;
        }
    }
}

// ---------------------------------------------------------------------------
// K4: fused zero + ones for Ri and Ro. One block per matrix row.
// blockIdx [0,8192)   -> Ri row
// blockIdx [8192,16384)-> Ro row
// ---------------------------------------------------------------------------
__global__ void __launch_bounds__(256) k_riro(float* __restrict__ out) {
    int bid = blockIdx.x;
    int mat = bid >> 13;          // 0 = Ri, 1 = Ro
    int row = bid & (N_HITS - 1);
    int tid = threadIdx.x;

    size_t base = (mat == 0 ? OFF_RI : OFF_RO) + (size_t)row * E_MAXSZ;
    float4* p = (float4*)(out + base);
    const float4 z4 = make_float4(0.f, 0.f, 0.f, 0.f);
    #pragma unroll
    for (int k = 0; k < 8; k++)
        p[k * 256 + tid] = z4;

    __syncthreads();

    int t = g_trkInt[row];
    int c;
    const int* lst;
    if (mat == 0) { c = g_inCnt[t];  lst = g_inList[t];  }
    else          { c = g_outCnt[t]; lst = g_outList[t]; }
    if (c > LIST_CAP) c = LIST_CAP;
    for (int m = tid; m < c; m += 256)
        out[base + (size_t)lst[m]] = 1.0f;
}

// ---------------------------------------------------------------------------
extern "C" void kernel_launch(void* const* d_in, const int* in_sizes, int n_in,
                              void* d_out, int out_size) {
    const float* ed = (const float*)d_in[0];
    float* out = (float*)d_out;

    k_reset    <<<1, 1024>>>();
    k_prep     <<<32, 256>>>(ed, out);
    k_pairs    <<<1024, 256>>>();
    k_scan_emit<<<1, 1024>>>(out);
    k_riro     <<<16384, 256>>>(out);
}

// round 3
// speedup vs baseline: 1.4308x; 1.2449x over previous
#include <cuda_runtime.h>
#include <stdint.h>

#define N_HITS  8192
#define E_MAXSZ 8192
#define ROW_CAP 64
#define LIST_CAP 64

// Output layout (float32 elements), tuple flattened in order:
// X (8192x3), Ri (8192x8192), Ro (8192x8192), y (8192), edges (8192x2), edge_mask (8192)
#define OFF_X     ((size_t)0)
#define OFF_RI    ((size_t)24576)
#define OFF_RO    (OFF_RI + (size_t)N_HITS * (size_t)E_MAXSZ)
#define OFF_Y     (OFF_RO + (size_t)N_HITS * (size_t)E_MAXSZ)
#define OFF_EDGES (OFF_Y + (size_t)E_MAXSZ)
#define OFF_MASK  (OFF_EDGES + (size_t)2 * E_MAXSZ)

// ---- scratch (device globals; no allocations allowed) ----
__device__ float  g_phin[N_HITS];
__device__ float  g_zn[N_HITS];
__device__ float  g_track[N_HITS];
__device__ int    g_trkInt[N_HITS];
__device__ float  g_ev[N_HITS];
__device__ int    g_st[N_HITS];

__device__ int    g_stcnt[32];
__device__ float4 g_stdata[32][N_HITS];     // {phin, zn, idx_bits, ev}

__device__ int    g_rowcnt[N_HITS];
__device__ int    g_rowoff[N_HITS];
__device__ int    g_count;
__device__ int    g_rowj[N_HITS][ROW_CAP];

// per-track edge lists for the fused zero+scatter pass
__device__ int    g_inCnt[1024];            // edges e with track[dst[e]] == t  -> Ri rows
__device__ int    g_outCnt[1024];           // edges e with track[src[e]] == t  -> Ro rows
__device__ int    g_inList[1024][LIST_CAP];
__device__ int    g_outList[1024][LIST_CAP];

// ---------------------------------------------------------------------------
// K0: reset counters (must run every call: graph replays reuse globals)
// ---------------------------------------------------------------------------
__global__ void k_reset(void) {
    int t = threadIdx.x;
    if (t < 32) g_stcnt[t] = 0;
    g_inCnt[t]  = 0;
    g_outCnt[t] = 0;
}

// ---------------------------------------------------------------------------
// K1: per-hit normalize (write X), bucket by station
// ---------------------------------------------------------------------------
__global__ void k_prep(const float* __restrict__ ed, float* __restrict__ out) {
    int i = blockIdx.x * blockDim.x + threadIdx.x;
    if (i >= N_HITS) return;

    float ev  = ed[6 * i + 0];
    float x   = ed[6 * i + 1];
    float y   = ed[6 * i + 2];
    float z   = ed[6 * i + 3];
    float stf = ed[6 * i + 4];
    float trk = ed[6 * i + 5];

    // IEEE-exact f32 path (no fma contraction, rn division/sqrt)
    float xx = __fmul_rn(x, x);
    float yy = __fmul_rn(y, y);
    float r  = __fsqrt_rn(__fadd_rn(xx, yy));
    float phi = atan2f(x, y);

    float rn   = __fadd_rn(__fdiv_rn(__fmul_rn(2.0f, __fadd_rn(r,  -269.0f)),  312.0f), -1.0f);
    float phin = __fadd_rn(__fdiv_rn(__fmul_rn(2.0f, __fadd_rn(phi,  3.15f)),    6.3f), -1.0f);
    float zn   = __fadd_rn(__fdiv_rn(__fmul_rn(2.0f, __fadd_rn(z,  2386.0f)),  4772.0f), -1.0f);

    out[OFF_X + 3 * (size_t)i + 0] = rn;
    out[OFF_X + 3 * (size_t)i + 1] = phin;
    out[OFF_X + 3 * (size_t)i + 2] = zn;

    g_phin[i]   = phin;
    g_zn[i]     = zn;
    g_track[i]  = trk;
    g_trkInt[i] = (int)trk;
    g_ev[i]     = ev;
    int st      = (int)stf;
    g_st[i]     = st;

    if (st >= 0 && st < 32) {
        int slot = atomicAdd(&g_stcnt[st], 1);
        float4 d;
        d.x = phin; d.y = zn; d.z = __int_as_float(i); d.w = ev;
        g_stdata[st][slot] = d;
    }
}

// ---------------------------------------------------------------------------
// K2: warp-per-row candidate scan against station st+1; sort matches by j
// ---------------------------------------------------------------------------
__global__ void k_pairs(void) {
    int gtid = blockIdx.x * blockDim.x + threadIdx.x;
    int row  = gtid >> 5;
    int lane = gtid & 31;
    if (row >= N_HITS) return;

    int myMatch[16];
    int mycnt = 0;

    int s2 = g_st[row] + 1;
    if (s2 >= 0 && s2 < 32) {
        int n2 = g_stcnt[s2];
        float pi  = g_phin[row];
        float zi  = g_zn[row];
        float evi = g_ev[row];
        for (int k = lane; k < n2; k += 32) {
            float4 c = g_stdata[s2][k];
            float dphi = c.x - pi;
            float dz   = c.y - zi;
            bool ok = (c.w == evi) &
                      (dphi > -0.04f) & (dphi < 0.04f) &
                      (dz   > -0.03f) & (dz   < 0.03f);
            if (ok && mycnt < 16) myMatch[mycnt++] = __float_as_int(c.z);
        }
    }

    // warp exclusive scan of per-lane counts
    int off = mycnt;
    #pragma unroll
    for (int d = 1; d < 32; d <<= 1) {
        int v = __shfl_up_sync(0xFFFFFFFFu, off, d);
        if (lane >= d) off += v;
    }
    int total = __shfl_sync(0xFFFFFFFFu, off, 31);
    int excl  = off - mycnt;
    for (int m = 0; m < mycnt; m++) {
        int e = excl + m;
        if (e < ROW_CAP) g_rowj[row][e] = myMatch[m];
    }
    __syncwarp();

    if (lane == 0) {
        int cnt = total < ROW_CAP ? total : ROW_CAP;
        // insertion sort ascending by j (bucket order is nondeterministic;
        // this restores exact row-major nonzero order)
        for (int a = 1; a < cnt; a++) {
            int v = g_rowj[row][a];
            int b = a - 1;
            while (b >= 0 && g_rowj[row][b] > v) { g_rowj[row][b + 1] = g_rowj[row][b]; b--; }
            g_rowj[row][b + 1] = v;
        }
        g_rowcnt[row] = cnt;
    }
}

// ---------------------------------------------------------------------------
// K3: minimal global scan (grid=1, 1024 thr, 8 rows/thread): rowoff + count
// ---------------------------------------------------------------------------
__global__ void k_scan(void) {
    __shared__ int warpTot[32];
    int tid  = threadIdx.x;
    int lane = tid & 31;
    int wid  = tid >> 5;

    int base = tid * 8;
    int4 a = *(const int4*)&g_rowcnt[base];
    int4 b = *(const int4*)&g_rowcnt[base + 4];
    int loc[8] = {a.x, a.y, a.z, a.w, b.x, b.y, b.z, b.w};
    int acc = 0;
    #pragma unroll
    for (int m = 0; m < 8; m++) acc += loc[m];

    int inc = acc;
    #pragma unroll
    for (int d = 1; d < 32; d <<= 1) {
        int v = __shfl_up_sync(0xFFFFFFFFu, inc, d);
        if (lane >= d) inc += v;
    }
    if (lane == 31) warpTot[wid] = inc;
    __syncthreads();
    if (wid == 0) {
        int w = warpTot[lane];
        int wi = w;
        #pragma unroll
        for (int d = 1; d < 32; d <<= 1) {
            int v = __shfl_up_sync(0xFFFFFFFFu, wi, d);
            if (lane >= d) wi += v;
        }
        warpTot[lane] = wi - w;
        if (lane == 31) g_count = wi;
    }
    __syncthreads();
    int run = inc - acc + warpTot[wid];
    int off8[8];
    #pragma unroll
    for (int m = 0; m < 8; m++) { off8[m] = run; run += loc[m]; }
    *(int4*)&g_rowoff[base]     = make_int4(off8[0], off8[1], off8[2], off8[3]);
    *(int4*)&g_rowoff[base + 4] = make_int4(off8[4], off8[5], off8[6], off8[7]);
}

// ---------------------------------------------------------------------------
// K4: wide emit — one thread per row: edges, per-track lists, fill/mask/y
// ---------------------------------------------------------------------------
__global__ void k_emit(float* __restrict__ out) {
    int i = blockIdx.x * blockDim.x + threadIdx.x;
    if (i >= N_HITS) return;

    int count = g_count;
    int cnt   = g_rowcnt[i];
    int off   = g_rowoff[i];
    float ti  = g_track[i];
    int tsI   = g_trkInt[i];

    for (int q = 0; q < cnt; q++) {
        int e = off + q;
        if (e < E_MAXSZ) {
            int j = g_rowj[i][q];
            out[OFF_EDGES + 2 * (size_t)e + 0] = ti;
            out[OFF_EDGES + 2 * (size_t)e + 1] = g_track[j];
            int tdI = g_trkInt[j];
            int so = atomicAdd(&g_outCnt[tsI], 1);
            if (so < LIST_CAP) g_outList[tsI][so] = e;
            int si = atomicAdd(&g_inCnt[tdI], 1);
            if (si < LIST_CAP) g_inList[tdI][si] = e;
        }
    }

    // slot i bookkeeping: y, mask, fill (nonzero fill_value=0 -> track[0])
    out[OFF_Y + (size_t)i] = 0.0f;
    out[OFF_MASK + (size_t)i] = (i < count) ? 1.0f : 0.0f;
    if (i >= count) {
        float t0 = g_track[0];
        out[OFF_EDGES + 2 * (size_t)i + 0] = t0;
        out[OFF_EDGES + 2 * (size_t)i + 1] = t0;
    }
}

// ---------------------------------------------------------------------------
// K5: fused zero + ones for Ri and Ro. One block per matrix row.
// blockIdx [0,8192)    -> Ri row
// blockIdx [8192,16384) -> Ro row
// ---------------------------------------------------------------------------
__global__ void __launch_bounds__(256) k_riro(float* __restrict__ out) {
    int bid = blockIdx.x;
    int mat = bid >> 13;          // 0 = Ri, 1 = Ro
    int row = bid & (N_HITS - 1);
    int tid = threadIdx.x;

    size_t base = (mat == 0 ? OFF_RI : OFF_RO) + (size_t)row * E_MAXSZ;
    float4* p = (float4*)(out + base);
    const float4 z4 = make_float4(0.f, 0.f, 0.f, 0.f);
    #pragma unroll
    for (int k = 0; k < 8; k++)
        p[k * 256 + tid] = z4;

    __syncthreads();

    int t = g_trkInt[row];
    int c;
    const int* lst;
    if (mat == 0) { c = g_inCnt[t];  lst = g_inList[t];  }
    else          { c = g_outCnt[t]; lst = g_outList[t]; }
    if (c > LIST_CAP) c = LIST_CAP;
    for (int m = tid; m < c; m += 256)
        out[base + (size_t)lst[m]] = 1.0f;
}

// ---------------------------------------------------------------------------
extern "C" void kernel_launch(void* const* d_in, const int* in_sizes, int n_in,
                              void* d_out, int out_size) {
    const float* ed = (const float*)d_in[0];
    float* out = (float*)d_out;

    k_reset<<<1, 1024>>>();
    k_prep <<<32, 256>>>(ed, out);
    k_pairs<<<1024, 256>>>();
    k_scan <<<1, 1024>>>();
    k_emit <<<32, 256>>>(out);
    k_riro <<<16384, 256>>>(out);
}